// round 3
// baseline (speedup 1.0000x reference)
#include <cuda_runtime.h>
#include <math.h>

#define DIM 512
#define NF4 (DIM / 4)
#define TAU 0.1f
#define EPS_NORM 1e-12f
#define EPS_DENOM 1e-8f
#define MAX_POS 32768

__device__ double   g_neg_sum = 0.0;
__device__ unsigned g_done    = 0u;
__device__ float    g_pos_logit[MAX_POS];

__device__ __forceinline__ float block_reduce_sum(float v, float* part, int warps) {
    const int lane = threadIdx.x & 31;
    const int warp = threadIdx.x >> 5;
    #pragma unroll
    for (int o = 16; o > 0; o >>= 1) v += __shfl_xor_sync(0xffffffffu, v, o);
    if (lane == 0) part[warp] = v;
    __syncthreads();
    float r = 0.0f;
    for (int i = 0; i < warps; i++) r += part[i];
    __syncthreads();
    return r;
}

// ---------------------------------------------------------------------------
// Single fused kernel.
// Grid = [neg blocks | pos blocks | mix blocks]. 256 threads/block.
// Every block: normalize anchor into shared (L2-hit) -> do its work ->
// ticket counter; last block finalizes the loss and resets state.
// ---------------------------------------------------------------------------
template<int WARPS>
__global__ void __launch_bounds__(WARPS * 32) k_all(
    const float4* __restrict__ h,
    const float4* __restrict__ p,
    const float*  __restrict__ anchor,
    const int*    __restrict__ mix_idx,
    const int*    __restrict__ idx_a,
    const int*    __restrict__ idx_b,
    const float*  __restrict__ alpha_raw,
    const float*  __restrict__ beta_raw,
    int nb_neg, int nb_pos,
    int n_hard, int n_pos, int n_mix,
    int total_blocks,
    float* __restrict__ out)
{
    __shared__ float4 sav[NF4];     // normalized anchor (2 KB)
    __shared__ float  part[WARPS];
    __shared__ double dpart[WARPS];
    __shared__ bool   sh_last;
    __shared__ float  sh_S;

    const int tid  = threadIdx.x;
    const int warp = tid >> 5;
    const int lane = tid & 31;
    const int b    = blockIdx.x;

    // ---- per-block anchor normalization (anchor is L2-resident) ----
    {
        const float4* a4 = (const float4*)anchor;
        float4 av = make_float4(0.f, 0.f, 0.f, 0.f);
        float  ss = 0.0f;
        if (tid < NF4) {
            av = a4[tid];
            ss = av.x * av.x + av.y * av.y + av.z * av.z + av.w * av.w;
        }
        ss = block_reduce_sum(ss, part, WARPS);
        if (tid < NF4) {
            float inv = 1.0f / fmaxf(sqrtf(ss), EPS_NORM);
            sav[tid] = make_float4(av.x * inv, av.y * inv, av.z * inv, av.w * inv);
        }
        __syncthreads();
    }

    // ---- work ----
    if (b < nb_neg + nb_pos) {
        const bool    is_neg = (b < nb_neg);
        const int     bb     = is_neg ? b : b - nb_neg;
        const int     nrows  = is_neg ? n_hard : n_pos;
        const float4* base   = is_neg ? h : p;
        const int     row    = bb * WARPS + warp;

        float val = 0.0f;
        if (row < nrows) {
            const float4* r = base + (size_t)row * NF4;
            float dot = 0.0f, ss = 0.0f;
            #pragma unroll
            for (int i = 0; i < 4; i++) {
                float4 v = r[lane + 32 * i];
                float4 a = sav[lane + 32 * i];
                dot += v.x * a.x + v.y * a.y + v.z * a.z + v.w * a.w;
                ss  += v.x * v.x + v.y * v.y + v.z * v.z + v.w * v.w;
            }
            #pragma unroll
            for (int o = 16; o > 0; o >>= 1) {
                dot += __shfl_xor_sync(0xffffffffu, dot, o);
                ss  += __shfl_xor_sync(0xffffffffu, ss, o);
            }
            if (lane == 0) {
                float l = dot / (fmaxf(sqrtf(ss), EPS_NORM) * TAU);
                if (is_neg) val = expf(l);
                else        g_pos_logit[row] = l;
            }
        }
        if (is_neg) {
            if (lane == 0) part[warp] = val;
            __syncthreads();
            if (tid == 0) {
                float s = 0.0f;
                #pragma unroll
                for (int i = 0; i < WARPS; i++) s += part[i];
                atomicAdd(&g_neg_sum, (double)s);
            }
            __syncthreads();
        }
    } else {
        // ----- mix path: one synthesized negative per block -----
        const int j  = b - (nb_neg + nb_pos);          // 0 .. 2*n_mix-1
        const float* hs = (const float*)h;

        const bool active = (tid < NF4);
        float4 a = active ? sav[tid] : make_float4(0.f, 0.f, 0.f, 0.f);
        float4 v = make_float4(0.f, 0.f, 0.f, 0.f);

        if (j < n_mix) {
            int   m     = mix_idx[j];
            float alpha = alpha_raw[j] * 0.4f + 0.1f;
            float4 x = make_float4(0.f, 0.f, 0.f, 0.f);
            if (active) x = ((const float4*)(hs + (size_t)m * DIM))[tid];
            float ssx = block_reduce_sum(
                x.x * x.x + x.y * x.y + x.z * x.z + x.w * x.w, part, WARPS);
            float inv = (1.0f - alpha) / fmaxf(sqrtf(ssx), EPS_NORM);
            v.x = x.x * inv + alpha * a.x;
            v.y = x.y * inv + alpha * a.y;
            v.z = x.z * inv + alpha * a.z;
            v.w = x.w * inv + alpha * a.w;
        } else {
            int   jj   = j - n_mix;
            int   ia   = idx_a[jj];
            int   ib   = idx_b[jj];
            float beta = beta_raw[jj] * 0.4f + 0.3f;
            float4 xa = make_float4(0.f, 0.f, 0.f, 0.f);
            float4 xb = make_float4(0.f, 0.f, 0.f, 0.f);
            if (active) {
                xa = ((const float4*)(hs + (size_t)ia * DIM))[tid];
                xb = ((const float4*)(hs + (size_t)ib * DIM))[tid];
            }
            float ssa = block_reduce_sum(
                xa.x * xa.x + xa.y * xa.y + xa.z * xa.z + xa.w * xa.w, part, WARPS);
            float ssb = block_reduce_sum(
                xb.x * xb.x + xb.y * xb.y + xb.z * xb.z + xb.w * xb.w, part, WARPS);
            float inva = beta          / fmaxf(sqrtf(ssa), EPS_NORM);
            float invb = (1.0f - beta) / fmaxf(sqrtf(ssb), EPS_NORM);
            v.x = xa.x * inva + xb.x * invb;
            v.y = xa.y * inva + xb.y * invb;
            v.z = xa.z * inva + xb.z * invb;
            v.w = xa.w * inva + xb.w * invb;
        }

        float ssv = block_reduce_sum(
            v.x * v.x + v.y * v.y + v.z * v.z + v.w * v.w, part, WARPS);
        float dv = block_reduce_sum(
            v.x * a.x + v.y * a.y + v.z * a.z + v.w * a.w, part, WARPS);

        if (tid == 0) {
            float l = dv / (fmaxf(sqrtf(ssv), EPS_NORM) * TAU);
            atomicAdd(&g_neg_sum, (double)expf(l));
        }
        __syncthreads();
    }

    // ---- ticket: last block to finish does the finalize ----
    __threadfence();
    if (tid == 0)
        sh_last = (atomicAdd(&g_done, 1u) == (unsigned)(total_blocks - 1));
    __syncthreads();
    if (!sh_last) return;

    // ---- finalize (one block, 256 threads) ----
    if (tid == 0) sh_S = (float)atomicAdd(&g_neg_sum, 0.0) + EPS_DENOM;
    __syncthreads();
    const float S = sh_S;

    double acc = 0.0;
    for (int i = tid; i < n_pos; i += WARPS * 32) {
        float l = __ldcg(&g_pos_logit[i]);
        acc += (double)log1pf(S * expf(-l));
    }
    #pragma unroll
    for (int o = 16; o > 0; o >>= 1)
        acc += __shfl_xor_sync(0xffffffffu, acc, o);
    if (lane == 0) dpart[warp] = acc;
    __syncthreads();
    if (tid == 0) {
        double t = 0.0;
        #pragma unroll
        for (int i = 0; i < WARPS; i++) t += dpart[i];
        out[0] = (float)(t / (double)n_pos);
        // reset state for the next (graph-replayed) call
        g_neg_sum = 0.0;
        g_done    = 0u;
    }
}

extern "C" void kernel_launch(void* const* d_in, const int* in_sizes, int n_in,
                              void* d_out, int out_size) {
    const float* anchor    = (const float*)d_in[0];
    const float* positives = (const float*)d_in[1];
    const float* hardnegs  = (const float*)d_in[2];
    const int*   mix_idx   = (const int*)d_in[3];
    const int*   idx_a     = (const int*)d_in[4];
    const int*   idx_b     = (const int*)d_in[5];
    const float* alpha_raw = (const float*)d_in[6];
    const float* beta_raw  = (const float*)d_in[7];

    const int n_pos  = in_sizes[1] / DIM;
    const int n_hard = in_sizes[2] / DIM;
    const int n_mix  = in_sizes[3];

    constexpr int WARPS = 8;
    const int nb_neg = (n_hard + WARPS - 1) / WARPS;
    const int nb_pos = (n_pos  + WARPS - 1) / WARPS;
    const int grid   = nb_neg + nb_pos + 2 * n_mix;

    k_all<WARPS><<<grid, WARPS * 32>>>(
        (const float4*)hardnegs, (const float4*)positives, anchor,
        mix_idx, idx_a, idx_b, alpha_raw, beta_raw,
        nb_neg, nb_pos, n_hard, n_pos, n_mix,
        grid, (float*)d_out);
}